// round 16
// baseline (speedup 1.0000x reference)
#include <cuda_runtime.h>
#include <cuda_bf16.h>

// 16-qubit statevector simulator.
// State: 128 batch x 65536 complex64 = 64 MB in a __device__ scratch array.
// Each pass loads an 8192-amplitude tile (64 KB) into smem covering 13 "local"
// qubits (3 fixed bits select the tile), applies all scheduled gates locally,
// and writes back. CNOT ring order is preserved exactly across pass splits.

constexpr int NT   = 512;    // threads per block
constexpr int TILE = 8192;   // amplitudes per tile (13 local qubits)
constexpr int HALF = 4096;   // gate pairs per tile

__device__ float2 g_state[128 * 65536];   // 64 MB scratch
__device__ float2 g_rot[96 * 4];          // 6 layers x 16 wires x 2x2 complex
__device__ float  g_part[8 * 128 * 16];   // per-tile Z partial sums

__device__ __forceinline__ int ins0(int v, int pos) {
    return ((v >> pos) << (pos + 1)) | (v & ((1 << pos) - 1));
}

// Precompute Rot(phi,theta,omega) = RZ(omega) RY(theta) RZ(phi) matrices.
__global__ void prep_rot(const float* __restrict__ w) {
    int t = threadIdx.x;
    if (t < 96) {
        float phi = w[t * 3 + 0], th = w[t * 3 + 1], om = w[t * 3 + 2];
        float sn, c;
        sincosf(0.5f * th, &sn, &c);
        float al = 0.5f * (phi + om), be = 0.5f * (phi - om);
        float sa, ca, sb, cb;
        sincosf(al, &sa, &ca);
        sincosf(be, &sb, &cb);
        float2 m;
        m.x = c * ca;   m.y = -c * sa;  g_rot[t * 4 + 0] = m;  // m00 = e^{-i a} c
        m.x = -sn * cb; m.y = -sn * sb; g_rot[t * 4 + 1] = m;  // m01 = -e^{i b} s
        m.x = sn * cb;  m.y = -sn * sb; g_rot[t * 4 + 2] = m;  // m10 = e^{-i b} s
        m.x = c * ca;   m.y = c * sa;   g_rot[t * 4 + 3] = m;  // m11 = e^{i a} c
    }
}

// One tiled pass over the state.
//   f0<f1<f2 : the 3 fixed (tile-index) bits; remaining 13 bits are smem-local.
//   layer    : which layer's Rot matrices to use.
//   rot_lo..rot_hi : wires to apply Rot on (empty if rot_lo > rot_hi).
//   cnot_lo..cnot_hi : ring indices i -> CNOT(i, (i+r) & 15), applied in order.
//   mode: 0 = load/store, 1 = init product state (no load), 2 = measure (no store).
__global__ void pass_kernel(const float* __restrict__ x,
                            int f0, int f1, int f2,
                            int layer, int rot_lo, int rot_hi,
                            int cnot_lo, int cnot_hi, int r, int mode) {
    extern __shared__ float2 s[];
    const int tid = threadIdx.x;
    const int h   = blockIdx.x;       // tile id (values of fixed bits)
    const int b   = blockIdx.y;       // batch element
    const size_t base = (size_t)b << 16;
    const int fixed = ((h & 1) << f0) | (((h >> 1) & 1) << f1) | (((h >> 2) & 1) << f2);

    __shared__ float cf[16], sf[16];

    if (mode == 1) {
        // Product state from RY(x_q) embedding: amp(g) = prod_q (bit_q ? sin : cos)(x_q/2)
        if (tid < 16) {
            float xv = x[b * 16 + tid];
            sincosf(0.5f * xv, &sf[tid], &cf[tid]);
        }
        __syncthreads();
#pragma unroll
        for (int k = 0; k < TILE / NT; k++) {
            int v = tid + k * NT;
            int g = ins0(ins0(ins0(v, f0), f1), f2) | fixed;
            float a = 1.0f;
#pragma unroll
            for (int q = 0; q < 16; q++) a *= ((g >> q) & 1) ? sf[q] : cf[q];
            float2 t; t.x = a; t.y = 0.0f;
            s[v] = t;
        }
        __syncthreads();
    } else {
#pragma unroll
        for (int k = 0; k < TILE / NT; k++) {
            int v = tid + k * NT;
            int g = ins0(ins0(ins0(v, f0), f1), f2) | fixed;
            s[v] = g_state[base + g];
        }
        __syncthreads();
    }

    // Rot gates (single-qubit, commuting within a layer)
    for (int q = rot_lo; q <= rot_hi; q++) {
        int pos = q - (q > f0) - (q > f1) - (q > f2);
        const float2* m = &g_rot[(layer * 16 + q) * 4];
        float2 m00 = m[0], m01 = m[1], m10 = m[2], m11 = m[3];
        int lmask = (1 << pos) - 1;
#pragma unroll
        for (int k = 0; k < HALF / NT; k++) {
            int p  = tid + k * NT;
            int i0 = ((p & ~lmask) << 1) | (p & lmask);
            int i1 = i0 | (1 << pos);
            float2 a  = s[i0];
            float2 bb = s[i1];
            float2 r0, r1;
            r0.x = m00.x * a.x - m00.y * a.y + m01.x * bb.x - m01.y * bb.y;
            r0.y = m00.x * a.y + m00.y * a.x + m01.x * bb.y + m01.y * bb.x;
            r1.x = m10.x * a.x - m10.y * a.y + m11.x * bb.x - m11.y * bb.y;
            r1.y = m10.x * a.y + m10.y * a.x + m11.x * bb.y + m11.y * bb.x;
            s[i0] = r0;
            s[i1] = r1;
        }
        __syncthreads();
    }

    // CNOT ring segment, strictly in ring order i = cnot_lo..cnot_hi
    for (int i = cnot_lo; i <= cnot_hi; i++) {
        int c = i, t = (i + r) & 15;
        int pc = c - (c > f0) - (c > f1) - (c > f2);
        int pt = t - (t > f0) - (t > f1) - (t > f2);
        int lmask = (1 << pt) - 1;
#pragma unroll
        for (int k = 0; k < HALF / NT; k++) {
            int p  = tid + k * NT;
            int i0 = ((p & ~lmask) << 1) | (p & lmask);
            if ((i0 >> pc) & 1) {
                int i1 = i0 | (1 << pt);
                float2 tmp = s[i0];
                s[i0] = s[i1];
                s[i1] = tmp;
            }
        }
        __syncthreads();
    }

    if (mode == 2) {
        // <Z_q> partials: sum |amp|^2 * (1 - 2*bit_q)
        float z[16];
#pragma unroll
        for (int q = 0; q < 16; q++) z[q] = 0.0f;
#pragma unroll
        for (int k = 0; k < TILE / NT; k++) {
            int v = tid + k * NT;
            int g = ins0(ins0(ins0(v, f0), f1), f2) | fixed;
            float2 a = s[v];
            float pr = a.x * a.x + a.y * a.y;
#pragma unroll
            for (int q = 0; q < 16; q++) z[q] += ((g >> q) & 1) ? -pr : pr;
        }
#pragma unroll
        for (int q = 0; q < 16; q++) {
#pragma unroll
            for (int o = 16; o > 0; o >>= 1)
                z[q] += __shfl_down_sync(0xffffffffu, z[q], o);
        }
        __shared__ float zs[NT / 32][16];
        int warp = tid >> 5, lane = tid & 31;
        if (lane == 0) {
#pragma unroll
            for (int q = 0; q < 16; q++) zs[warp][q] = z[q];
        }
        __syncthreads();
        if (tid < 16) {
            float acc = 0.0f;
#pragma unroll
            for (int wp = 0; wp < NT / 32; wp++) acc += zs[wp][tid];
            g_part[(h * 128 + b) * 16 + tid] = acc;
        }
    } else {
#pragma unroll
        for (int k = 0; k < TILE / NT; k++) {
            int v = tid + k * NT;
            int g = ins0(ins0(ins0(v, f0), f1), f2) | fixed;
            g_state[base + g] = s[v];
        }
    }
}

__global__ void finalize_kernel(float* __restrict__ out) {
    int i = blockIdx.x * blockDim.x + threadIdx.x;
    if (i < 2048) {
        float a = 0.0f;
#pragma unroll
        for (int hh = 0; hh < 8; hh++) a += g_part[hh * 2048 + i];
        out[i] = a;
    }
}

extern "C" void kernel_launch(void* const* d_in, const int* in_sizes, int n_in,
                              void* d_out, int out_size) {
    const float* x = (const float*)d_in[0];
    const float* w = (const float*)d_in[1];
    if (n_in >= 2 && in_sizes[0] == 288) {  // defensive: inputs swapped
        const float* t = x; x = w; w = t;
    }
    float* out = (float*)d_out;

    cudaFuncSetAttribute(pass_kernel, cudaFuncAttributeMaxDynamicSharedMemorySize, 65536);

    prep_rot<<<1, 96>>>(w);

    dim3 grid(8, 128);
    const int SM = 65536;

    // Layer 0 (r=1): init + Rot0..12 + CNOT i=0..11 | HIGH F{3,4,5}: Rot13..15 + i=12..15
    pass_kernel<<<grid, NT, SM>>>(x, 13, 14, 15, 0, 0, 12, 0, 11, 1, 1);
    pass_kernel<<<grid, NT, SM>>>(x, 3, 4, 5,    0, 13, 15, 12, 15, 1, 0);
    // Layer 1 (r=2)
    pass_kernel<<<grid, NT, SM>>>(x, 13, 14, 15, 1, 0, 12, 0, 10, 2, 0);
    pass_kernel<<<grid, NT, SM>>>(x, 3, 4, 5,    1, 13, 15, 11, 15, 2, 0);
    // Layer 2 (r=3)
    pass_kernel<<<grid, NT, SM>>>(x, 13, 14, 15, 2, 0, 12, 0, 9, 3, 0);
    pass_kernel<<<grid, NT, SM>>>(x, 3, 4, 5,    2, 13, 15, 10, 15, 3, 0);
    // Layer 3 (r=4): deferred suffix touches qubit 3 -> fixed bits {4,5,6}
    pass_kernel<<<grid, NT, SM>>>(x, 13, 14, 15, 3, 0, 12, 0, 8, 4, 0);
    pass_kernel<<<grid, NT, SM>>>(x, 4, 5, 6,    3, 13, 15, 9, 15, 4, 0);
    // Layer 4 (r=5): fixed bits {5,6,7}
    pass_kernel<<<grid, NT, SM>>>(x, 13, 14, 15, 4, 0, 12, 0, 7, 5, 0);
    pass_kernel<<<grid, NT, SM>>>(x, 5, 6, 7,    4, 13, 15, 8, 15, 5, 0);
    // Layer 5 (r=6): suffix needs 15 qubits -> split into two HIGH passes
    pass_kernel<<<grid, NT, SM>>>(x, 13, 14, 15, 5, 0, 12, 0, 6, 6, 0);
    pass_kernel<<<grid, NT, SM>>>(x, 3, 4, 5,    5, 13, 15, 7, 9, 6, 0);
    // Final pass: remaining CNOTs i=10..15 (fixed {6,7,8}) + fused measurement
    pass_kernel<<<grid, NT, SM>>>(x, 6, 7, 8,    5, 1, 0, 10, 15, 6, 2);

    finalize_kernel<<<8, 256>>>(out);
}

// round 17
// speedup vs baseline: 1.0000x; 1.0000x over previous
#include <cuda_runtime.h>
#include <cuda_bf16.h>

// 16-qubit statevector simulator.
// State: 128 batch x 65536 complex64 = 64 MB in a __device__ scratch array.
// Each pass loads an 8192-amplitude tile (64 KB) into smem covering 13 "local"
// qubits (3 fixed bits select the tile), applies all scheduled gates locally,
// and writes back. CNOT ring order is preserved exactly across pass splits.

constexpr int NT   = 512;    // threads per block
constexpr int TILE = 8192;   // amplitudes per tile (13 local qubits)
constexpr int HALF = 4096;   // gate pairs per tile

__device__ float2 g_state[128 * 65536];   // 64 MB scratch
__device__ float2 g_rot[96 * 4];          // 6 layers x 16 wires x 2x2 complex
__device__ float  g_part[8 * 128 * 16];   // per-tile Z partial sums

__device__ __forceinline__ int ins0(int v, int pos) {
    return ((v >> pos) << (pos + 1)) | (v & ((1 << pos) - 1));
}

// Precompute Rot(phi,theta,omega) = RZ(omega) RY(theta) RZ(phi) matrices.
__global__ void prep_rot(const float* __restrict__ w) {
    int t = threadIdx.x;
    if (t < 96) {
        float phi = w[t * 3 + 0], th = w[t * 3 + 1], om = w[t * 3 + 2];
        float sn, c;
        sincosf(0.5f * th, &sn, &c);
        float al = 0.5f * (phi + om), be = 0.5f * (phi - om);
        float sa, ca, sb, cb;
        sincosf(al, &sa, &ca);
        sincosf(be, &sb, &cb);
        float2 m;
        m.x = c * ca;   m.y = -c * sa;  g_rot[t * 4 + 0] = m;  // m00 = e^{-i a} c
        m.x = -sn * cb; m.y = -sn * sb; g_rot[t * 4 + 1] = m;  // m01 = -e^{i b} s
        m.x = sn * cb;  m.y = -sn * sb; g_rot[t * 4 + 2] = m;  // m10 = e^{-i b} s
        m.x = c * ca;   m.y = c * sa;   g_rot[t * 4 + 3] = m;  // m11 = e^{i a} c
    }
}

// One tiled pass over the state.
//   f0<f1<f2 : the 3 fixed (tile-index) bits; remaining 13 bits are smem-local.
//   layer    : which layer's Rot matrices to use.
//   rot_lo..rot_hi : wires to apply Rot on (empty if rot_lo > rot_hi).
//   cnot_lo..cnot_hi : ring indices i -> CNOT(i, (i+r) & 15), applied in order.
//   mode: 0 = load/store, 1 = init product state (no load), 2 = measure (no store).
__global__ void pass_kernel(const float* __restrict__ x,
                            int f0, int f1, int f2,
                            int layer, int rot_lo, int rot_hi,
                            int cnot_lo, int cnot_hi, int r, int mode) {
    extern __shared__ float2 s[];
    const int tid = threadIdx.x;
    const int h   = blockIdx.x;       // tile id (values of fixed bits)
    const int b   = blockIdx.y;       // batch element
    const size_t base = (size_t)b << 16;
    const int fixed = ((h & 1) << f0) | (((h >> 1) & 1) << f1) | (((h >> 2) & 1) << f2);

    __shared__ float cf[16], sf[16];

    if (mode == 1) {
        // Product state from RY(x_q) embedding: amp(g) = prod_q (bit_q ? sin : cos)(x_q/2)
        if (tid < 16) {
            float xv = x[b * 16 + tid];
            sincosf(0.5f * xv, &sf[tid], &cf[tid]);
        }
        __syncthreads();
#pragma unroll
        for (int k = 0; k < TILE / NT; k++) {
            int v = tid + k * NT;
            int g = ins0(ins0(ins0(v, f0), f1), f2) | fixed;
            float a = 1.0f;
#pragma unroll
            for (int q = 0; q < 16; q++) a *= ((g >> q) & 1) ? sf[q] : cf[q];
            float2 t; t.x = a; t.y = 0.0f;
            s[v] = t;
        }
        __syncthreads();
    } else {
#pragma unroll
        for (int k = 0; k < TILE / NT; k++) {
            int v = tid + k * NT;
            int g = ins0(ins0(ins0(v, f0), f1), f2) | fixed;
            s[v] = g_state[base + g];
        }
        __syncthreads();
    }

    // Rot gates (single-qubit, commuting within a layer)
    for (int q = rot_lo; q <= rot_hi; q++) {
        int pos = q - (q > f0) - (q > f1) - (q > f2);
        const float2* m = &g_rot[(layer * 16 + q) * 4];
        float2 m00 = m[0], m01 = m[1], m10 = m[2], m11 = m[3];
        int lmask = (1 << pos) - 1;
#pragma unroll
        for (int k = 0; k < HALF / NT; k++) {
            int p  = tid + k * NT;
            int i0 = ((p & ~lmask) << 1) | (p & lmask);
            int i1 = i0 | (1 << pos);
            float2 a  = s[i0];
            float2 bb = s[i1];
            float2 r0, r1;
            r0.x = m00.x * a.x - m00.y * a.y + m01.x * bb.x - m01.y * bb.y;
            r0.y = m00.x * a.y + m00.y * a.x + m01.x * bb.y + m01.y * bb.x;
            r1.x = m10.x * a.x - m10.y * a.y + m11.x * bb.x - m11.y * bb.y;
            r1.y = m10.x * a.y + m10.y * a.x + m11.x * bb.y + m11.y * bb.x;
            s[i0] = r0;
            s[i1] = r1;
        }
        __syncthreads();
    }

    // CNOT ring segment, strictly in ring order i = cnot_lo..cnot_hi
    for (int i = cnot_lo; i <= cnot_hi; i++) {
        int c = i, t = (i + r) & 15;
        int pc = c - (c > f0) - (c > f1) - (c > f2);
        int pt = t - (t > f0) - (t > f1) - (t > f2);
        int lmask = (1 << pt) - 1;
#pragma unroll
        for (int k = 0; k < HALF / NT; k++) {
            int p  = tid + k * NT;
            int i0 = ((p & ~lmask) << 1) | (p & lmask);
            if ((i0 >> pc) & 1) {
                int i1 = i0 | (1 << pt);
                float2 tmp = s[i0];
                s[i0] = s[i1];
                s[i1] = tmp;
            }
        }
        __syncthreads();
    }

    if (mode == 2) {
        // <Z_q> partials: sum |amp|^2 * (1 - 2*bit_q)
        float z[16];
#pragma unroll
        for (int q = 0; q < 16; q++) z[q] = 0.0f;
#pragma unroll
        for (int k = 0; k < TILE / NT; k++) {
            int v = tid + k * NT;
            int g = ins0(ins0(ins0(v, f0), f1), f2) | fixed;
            float2 a = s[v];
            float pr = a.x * a.x + a.y * a.y;
#pragma unroll
            for (int q = 0; q < 16; q++) z[q] += ((g >> q) & 1) ? -pr : pr;
        }
#pragma unroll
        for (int q = 0; q < 16; q++) {
#pragma unroll
            for (int o = 16; o > 0; o >>= 1)
                z[q] += __shfl_down_sync(0xffffffffu, z[q], o);
        }
        __shared__ float zs[NT / 32][16];
        int warp = tid >> 5, lane = tid & 31;
        if (lane == 0) {
#pragma unroll
            for (int q = 0; q < 16; q++) zs[warp][q] = z[q];
        }
        __syncthreads();
        if (tid < 16) {
            float acc = 0.0f;
#pragma unroll
            for (int wp = 0; wp < NT / 32; wp++) acc += zs[wp][tid];
            g_part[(h * 128 + b) * 16 + tid] = acc;
        }
    } else {
#pragma unroll
        for (int k = 0; k < TILE / NT; k++) {
            int v = tid + k * NT;
            int g = ins0(ins0(ins0(v, f0), f1), f2) | fixed;
            g_state[base + g] = s[v];
        }
    }
}

__global__ void finalize_kernel(float* __restrict__ out) {
    int i = blockIdx.x * blockDim.x + threadIdx.x;
    if (i < 2048) {
        float a = 0.0f;
#pragma unroll
        for (int hh = 0; hh < 8; hh++) a += g_part[hh * 2048 + i];
        out[i] = a;
    }
}

extern "C" void kernel_launch(void* const* d_in, const int* in_sizes, int n_in,
                              void* d_out, int out_size) {
    const float* x = (const float*)d_in[0];
    const float* w = (const float*)d_in[1];
    if (n_in >= 2 && in_sizes[0] == 288) {  // defensive: inputs swapped
        const float* t = x; x = w; w = t;
    }
    float* out = (float*)d_out;

    cudaFuncSetAttribute(pass_kernel, cudaFuncAttributeMaxDynamicSharedMemorySize, 65536);

    prep_rot<<<1, 96>>>(w);

    dim3 grid(8, 128);
    const int SM = 65536;

    // Layer 0 (r=1): init + Rot0..12 + CNOT i=0..11 | HIGH F{3,4,5}: Rot13..15 + i=12..15
    pass_kernel<<<grid, NT, SM>>>(x, 13, 14, 15, 0, 0, 12, 0, 11, 1, 1);
    pass_kernel<<<grid, NT, SM>>>(x, 3, 4, 5,    0, 13, 15, 12, 15, 1, 0);
    // Layer 1 (r=2)
    pass_kernel<<<grid, NT, SM>>>(x, 13, 14, 15, 1, 0, 12, 0, 10, 2, 0);
    pass_kernel<<<grid, NT, SM>>>(x, 3, 4, 5,    1, 13, 15, 11, 15, 2, 0);
    // Layer 2 (r=3)
    pass_kernel<<<grid, NT, SM>>>(x, 13, 14, 15, 2, 0, 12, 0, 9, 3, 0);
    pass_kernel<<<grid, NT, SM>>>(x, 3, 4, 5,    2, 13, 15, 10, 15, 3, 0);
    // Layer 3 (r=4): deferred suffix touches qubit 3 -> fixed bits {4,5,6}
    pass_kernel<<<grid, NT, SM>>>(x, 13, 14, 15, 3, 0, 12, 0, 8, 4, 0);
    pass_kernel<<<grid, NT, SM>>>(x, 4, 5, 6,    3, 13, 15, 9, 15, 4, 0);
    // Layer 4 (r=5): fixed bits {5,6,7}
    pass_kernel<<<grid, NT, SM>>>(x, 13, 14, 15, 4, 0, 12, 0, 7, 5, 0);
    pass_kernel<<<grid, NT, SM>>>(x, 5, 6, 7,    4, 13, 15, 8, 15, 5, 0);
    // Layer 5 (r=6): suffix needs 15 qubits -> split into two HIGH passes
    pass_kernel<<<grid, NT, SM>>>(x, 13, 14, 15, 5, 0, 12, 0, 6, 6, 0);
    pass_kernel<<<grid, NT, SM>>>(x, 3, 4, 5,    5, 13, 15, 7, 9, 6, 0);
    // Final pass: remaining CNOTs i=10..15 (fixed {6,7,8}) + fused measurement
    pass_kernel<<<grid, NT, SM>>>(x, 6, 7, 8,    5, 1, 0, 10, 15, 6, 2);

    finalize_kernel<<<8, 256>>>(out);
}